// round 2
// baseline (speedup 1.0000x reference)
#include <cuda_runtime.h>

#define BATCH 64
#define NPTS  100000
#define KB    32      // reduction blocks per batch
#define TPB   256

// per-(batch, block) partial moment tables S[6][6]
__device__ float g_part[BATCH * KB * 36];

// ---------------------------------------------------------------------------
// Kernel 1: weighted moment reduction.
// S[p][q] = sum_n w * nn_p * mm_q, nn = {x2^2, x2*y2, y2^2, x2, y2, 1},
//                                  mm = {x1^2, x1*y1, y1^2, x1, y1, 1}
// ---------------------------------------------------------------------------
__global__ void __launch_bounds__(TPB) reduce_kernel(const float4* __restrict__ x,
                                                     const float*  __restrict__ lg) {
    int b   = blockIdx.y;
    int blk = blockIdx.x;
    const float4* xb = x  + (size_t)b * NPTS;
    const float*  lb = lg + (size_t)b * NPTS;
    const int chunk = (NPTS + KB - 1) / KB;   // 3125
    int start = blk * chunk;
    int end   = min(NPTS, start + chunk);

    float acc[36];
#pragma unroll
    for (int k = 0; k < 36; k++) acc[k] = 0.f;

    for (int i = start + (int)threadIdx.x; i < end; i += TPB) {
        float4 p = xb[i];
        float w  = tanhf(lb[i]);
        w = fmaxf(w, 0.f);
        float x1 = p.x, y1 = p.y, x2 = p.z, y2 = p.w;
        float mmv[6] = {x1 * x1, x1 * y1, y1 * y1, x1, y1, 1.f};
        float wn[6];
        wn[0] = w * (x2 * x2);
        wn[1] = w * (x2 * y2);
        wn[2] = w * (y2 * y2);
        wn[3] = w * x2;
        wn[4] = w * y2;
        wn[5] = w;
#pragma unroll
        for (int pI = 0; pI < 6; pI++)
#pragma unroll
            for (int q = 0; q < 6; q++)
                acc[pI * 6 + q] = fmaf(wn[pI], mmv[q], acc[pI * 6 + q]);
    }

    // warp tree reduce (deterministic)
#pragma unroll
    for (int k = 0; k < 36; k++) {
#pragma unroll
        for (int off = 16; off > 0; off >>= 1)
            acc[k] += __shfl_xor_sync(0xffffffffu, acc[k], off);
    }

    __shared__ float sm[TPB / 32][36];
    int wid = threadIdx.x >> 5, lane = threadIdx.x & 31;
    if (lane == 0) {
#pragma unroll
        for (int k = 0; k < 36; k++) sm[wid][k] = acc[k];
    }
    __syncthreads();
    if (threadIdx.x < 36) {
        float s = 0.f;
#pragma unroll
        for (int w8 = 0; w8 < TPB / 32; w8++) s += sm[w8][threadIdx.x];
        g_part[(b * KB + blk) * 36 + threadIdx.x] = s;
    }
}

// ---------------------------------------------------------------------------
// LAPACK ssyevd emulation helpers (fp32, netlib conventions)
// ---------------------------------------------------------------------------
// faithful slapy2: w=max, z=min, w*sqrt(1+(z/w)^2)
__device__ __forceinline__ float slapy2f(float xx, float yy) {
    float xa = fabsf(xx), ya = fabsf(yy);
    float w = fmaxf(xa, ya);
    float z = fminf(xa, ya);
    if (z == 0.f) return w;
    float q = z / w;
    return w * sqrtf(1.f + q * q);
}

// modern (LAPACK >= 3.10) slartg
__device__ __forceinline__ void slartg_(float f, float g, float& c, float& s, float& r) {
    if (g == 0.f) { c = 1.f; s = 0.f; r = f; }
    else if (f == 0.f) { c = 0.f; s = copysignf(1.f, g); r = fabsf(g); }
    else {
        float dd = sqrtf(f * f + g * g);
        c = fabsf(f) / dd;
        r = copysignf(dd, f);
        s = g / r;
    }
}

__device__ void slaev2_(float a, float b, float c,
                        float& rt1, float& rt2, float& cs1, float& sn1) {
    float sm = a + c, df = a - c, adf = fabsf(df);
    float tb = b + b, ab = fabsf(tb);
    float acmx, acmn;
    if (fabsf(a) > fabsf(c)) { acmx = a; acmn = c; } else { acmx = c; acmn = a; }
    float rt;
    if (adf > ab)      { float q = ab / adf; rt = adf * sqrtf(1.f + q * q); }
    else if (adf < ab) { float q = adf / ab; rt = ab * sqrtf(1.f + q * q); }
    else               { rt = ab * sqrtf(2.f); }
    int sgn1;
    if (sm < 0.f)      { rt1 = 0.5f * (sm - rt); sgn1 = -1; rt2 = (acmx / rt1) * acmn - (b / rt1) * b; }
    else if (sm > 0.f) { rt1 = 0.5f * (sm + rt); sgn1 =  1; rt2 = (acmx / rt1) * acmn - (b / rt1) * b; }
    else               { rt1 = 0.5f * rt; rt2 = -0.5f * rt; sgn1 = 1; }
    int sgn2; float cs;
    if (df >= 0.f) { cs = df + rt; sgn2 = 1; } else { cs = df - rt; sgn2 = -1; }
    float acs = fabsf(cs);
    if (acs > ab) {
        float ct = -tb / cs;
        sn1 = 1.f / sqrtf(1.f + ct * ct);
        cs1 = ct * sn1;
    } else {
        if (ab == 0.f) { cs1 = 1.f; sn1 = 0.f; }
        else {
            float tn = -cs / tb;
            cs1 = 1.f / sqrtf(1.f + tn * tn);
            sn1 = tn * cs1;
        }
    }
    if (sgn1 == sgn2) { float tn = cs1; cs1 = -sn1; sn1 = tn; }
}

// apply rotation (dlasr 'R','V' inner formula) to z columns (col, col+1)
__device__ __forceinline__ void rot_cols(float z[9][9], int col, float c, float s) {
#pragma unroll
    for (int r = 0; r < 9; r++) {
        float t = z[r][col + 1];
        z[r][col + 1] = c * t - s * z[r][col];
        z[r][col]     = s * t + c * z[r][col];
    }
}

// ---------------------------------------------------------------------------
// Kernel 2: assemble 9x9, ssytrd + form Q + ssteqr (LAPACK-faithful), output
// the eigenvector of the smallest eigenvalue, normalized.
// ---------------------------------------------------------------------------
__global__ void solve_kernel(float* __restrict__ out) {
    int b = blockIdx.x;
    __shared__ float S[36];
    int t = threadIdx.x;
    if (t < 36) {
        float s = 0.f;
        for (int k = 0; k < KB; k++) s += g_part[(b * KB + k) * 36 + t];
        S[t] = s;
    }
    __syncthreads();
    if (t != 0) return;

    const int n = 9;
    // reconstruct 9x9: M[3a+bb][3c+dd] = S[P[a][c]][P[bb][dd]]
    const int P[3][3] = {{0, 1, 3}, {1, 2, 4}, {3, 4, 5}};
    float A[9][9];
    for (int i = 0; i < 9; i++) {
        int a = i / 3, bb = i % 3;
        for (int j = 0; j < 9; j++) {
            int c = j / 3, dd = j % 3;
            A[i][j] = S[P[a][c] * 6 + P[bb][dd]];
        }
    }

    float d[9], e[9], tau[8];

    // ---- ssytrd (uplo='L', unblocked ssytd2) ----
    for (int i = 0; i < n - 1; i++) {
        float alpha = A[i + 1][i];
        float xn2 = 0.f;
        for (int k = i + 2; k < n; k++) xn2 += A[k][i] * A[k][i];
        float taui, beta;
        if (xn2 == 0.f) { taui = 0.f; beta = alpha; }
        else {
            beta = -copysignf(slapy2f(alpha, sqrtf(xn2)), alpha);
            taui = (beta - alpha) / beta;
            float inv = 1.f / (alpha - beta);
            for (int k = i + 2; k < n; k++) A[k][i] *= inv;
        }
        e[i] = beta;
        tau[i] = taui;
        if (taui != 0.f) {
            float v[9], w[9];
            v[i + 1] = 1.f;
            for (int k = i + 2; k < n; k++) v[k] = A[k][i];
            // w = taui * A22 * v
            for (int r = i + 1; r < n; r++) {
                float s = 0.f;
                for (int cc = i + 1; cc < n; cc++) s += A[r][cc] * v[cc];
                w[r] = taui * s;
            }
            float dot = 0.f;
            for (int r = i + 1; r < n; r++) dot += w[r] * v[r];
            float al = -0.5f * taui * dot;
            for (int r = i + 1; r < n; r++) w[r] += al * v[r];
            for (int r = i + 1; r < n; r++)
                for (int cc = i + 1; cc < n; cc++)
                    A[r][cc] -= v[r] * w[cc] + w[r] * v[cc];
        }
    }
    for (int k = 0; k < n; k++) d[k] = A[k][k];

    // ---- form Q = H(0) H(1) ... H(n-2) ----
    float z[9][9];
    for (int r = 0; r < 9; r++)
        for (int c = 0; c < 9; c++) z[r][c] = (r == c) ? 1.f : 0.f;
    for (int i = n - 2; i >= 0; i--) {
        if (tau[i] == 0.f) continue;
        float u[9];
        u[i + 1] = 1.f;
        for (int k = i + 2; k < n; k++) u[k] = A[k][i];
        for (int c = 0; c < n; c++) {
            float s = 0.f;
            for (int r = i + 1; r < n; r++) s += u[r] * z[r][c];
            s *= tau[i];
            for (int r = i + 1; r < n; r++) z[r][c] -= u[r] * s;
        }
    }

    // ---- ssteqr (netlib-faithful, no scaling branch) ----
    const float eps = 5.9604645e-08f;   // SLAMCH('E') = 2^-24 (round-mode epsilon)
    const float eps2 = eps * eps;
    const float safmin = 1.17549435e-38f;
    const int nmaxit = n * 30;
    int jtot = 0;
    int l1 = 0;
    while (l1 < n) {
        if (l1 > 0) e[l1 - 1] = 0.f;
        int m = n - 1;
        for (int k = l1; k < n - 1; k++) {
            float tst = fabsf(e[k]);
            if (tst == 0.f) { m = k; break; }
            if (tst <= (sqrtf(fabsf(d[k])) * sqrtf(fabsf(d[k + 1]))) * eps) {
                e[k] = 0.f; m = k; break;
            }
        }
        int l = l1, lsv = l, lend = m, lendsv = lend;
        l1 = m + 1;
        if (lend == l) continue;
        if (fabsf(d[lend]) < fabsf(d[l])) { lend = lsv; l = lendsv; }

        if (lend > l) {
            // --- QL iteration ---
            for (;;) {
                int mm = lend;
                if (l != lend) {
                    for (int k = l; k <= lend - 1; k++) {
                        float tst = e[k] * e[k];
                        if (tst <= (eps2 * fabsf(d[k])) * fabsf(d[k + 1]) + safmin) { mm = k; break; }
                    }
                }
                if (mm < lend) e[mm] = 0.f;
                float p = d[l];
                if (mm == l) {
                    d[l] = p; l++;
                    if (l <= lend) continue; else break;
                }
                if (mm == l + 1) {
                    float rt1, rt2, c, s;
                    slaev2_(d[l], e[l], d[l + 1], rt1, rt2, c, s);
                    rot_cols(z, l, c, s);
                    d[l] = rt1; d[l + 1] = rt2; e[l] = 0.f;
                    l += 2;
                    if (l <= lend) continue; else break;
                }
                if (jtot == nmaxit) break;
                jtot++;
                float g = (d[l + 1] - p) / (2.f * e[l]);
                float r = slapy2f(g, 1.f);
                g = d[mm] - p + e[l] / (g + copysignf(r, g));
                float s = 1.f, c = 1.f;
                p = 0.f;
                for (int i = mm - 1; i >= l; i--) {
                    float f = s * e[i];
                    float bb = c * e[i];
                    slartg_(g, f, c, s, r);
                    if (i != mm - 1) e[i + 1] = r;
                    g = d[i + 1] - p;
                    r = (d[i] - g) * s + 2.f * c * bb;
                    p = s * r;
                    d[i + 1] = g + p;
                    g = c * r - bb;
                    rot_cols(z, i, c, -s);   // WORK stores -S, applied 'B'
                }
                d[l] -= p;
                e[l] = g;
            }
        } else {
            // --- QR iteration ---
            for (;;) {
                int mm = lend;
                if (l != lend) {
                    for (int k = l; k >= lend + 1; k--) {
                        float tst = e[k - 1] * e[k - 1];
                        if (tst <= (eps2 * fabsf(d[k])) * fabsf(d[k - 1]) + safmin) { mm = k; break; }
                    }
                }
                if (mm > lend) e[mm - 1] = 0.f;
                float p = d[l];
                if (mm == l) {
                    d[l] = p; l--;
                    if (l >= lend) continue; else break;
                }
                if (mm == l - 1) {
                    float rt1, rt2, c, s;
                    slaev2_(d[l - 1], e[l - 1], d[l], rt1, rt2, c, s);
                    rot_cols(z, l - 1, c, s);
                    d[l - 1] = rt1; d[l] = rt2; e[l - 1] = 0.f;
                    l -= 2;
                    if (l >= lend) continue; else break;
                }
                if (jtot == nmaxit) break;
                jtot++;
                float g = (d[l - 1] - p) / (2.f * e[l - 1]);
                float r = slapy2f(g, 1.f);
                g = d[mm] - p + e[l - 1] / (g + copysignf(r, g));
                float s = 1.f, c = 1.f;
                p = 0.f;
                for (int i = mm; i <= l - 1; i++) {
                    float f = s * e[i];
                    float bb = c * e[i];
                    slartg_(g, f, c, s, r);
                    if (i != mm) e[i - 1] = r;
                    g = d[i] - p;
                    r = (d[i + 1] - g) * s + 2.f * c * bb;
                    p = s * r;
                    d[i] = g + p;
                    g = c * r - bb;
                    rot_cols(z, i, c, s);    // WORK stores +S, applied 'F'
                }
                d[l] -= p;
                e[l - 1] = g;
            }
        }
    }

    // ---- selection sort ascending (swaps eigenvector columns) ----
    for (int ii = 1; ii < n; ii++) {
        int i = ii - 1, k = i;
        float p = d[i];
        for (int j = ii; j < n; j++)
            if (d[j] < p) { k = j; p = d[j]; }
        if (k != i) {
            d[k] = d[i]; d[i] = p;
            for (int r = 0; r < n; r++) {
                float tz = z[r][i]; z[r][i] = z[r][k]; z[r][k] = tz;
            }
        }
    }

    // ---- output: first column (smallest eigenvalue), normalized ----
    float nrm2 = 0.f;
    for (int r = 0; r < n; r++) nrm2 += z[r][0] * z[r][0];
    float inv = 1.f / sqrtf(nrm2);
    for (int r = 0; r < n; r++) out[b * 9 + r] = z[r][0] * inv;
}

// ---------------------------------------------------------------------------
extern "C" void kernel_launch(void* const* d_in, const int* in_sizes, int n_in,
                              void* d_out, int out_size) {
    const float4* x  = (const float4*)d_in[0];
    const float*  lg = (const float*)d_in[1];
    float* out = (float*)d_out;
    dim3 grid(KB, BATCH);
    reduce_kernel<<<grid, TPB>>>(x, lg);
    solve_kernel<<<BATCH, 64>>>(out);
}

// round 4
// speedup vs baseline: 1.3606x; 1.3606x over previous
#include <cuda_runtime.h>

#define BATCH 64
#define NPTS  100000
#define KB    32      // reduction blocks per batch
#define TPB   256

// per-(batch, block) partial moment tables S[6][6]
__device__ float g_part[BATCH * KB * 36];

// ---------------------------------------------------------------------------
// Kernel 1: weighted moment reduction — BITWISE IDENTICAL to round-2 pass.
// S[p][q] = sum_n w * nn_p * mm_q, nn = {x2^2, x2*y2, y2^2, x2, y2, 1},
//                                  mm = {x1^2, x1*y1, y1^2, x1, y1, 1}
// ---------------------------------------------------------------------------
__global__ void __launch_bounds__(TPB) reduce_kernel(const float4* __restrict__ x,
                                                     const float*  __restrict__ lg) {
    int b   = blockIdx.y;
    int blk = blockIdx.x;
    const float4* xb = x  + (size_t)b * NPTS;
    const float*  lb = lg + (size_t)b * NPTS;
    const int chunk = (NPTS + KB - 1) / KB;   // 3125
    int start = blk * chunk;
    int end   = min(NPTS, start + chunk);

    float acc[36];
#pragma unroll
    for (int k = 0; k < 36; k++) acc[k] = 0.f;

    for (int i = start + (int)threadIdx.x; i < end; i += TPB) {
        float4 p = xb[i];
        float w  = tanhf(lb[i]);
        w = fmaxf(w, 0.f);
        float x1 = p.x, y1 = p.y, x2 = p.z, y2 = p.w;
        float mmv[6] = {x1 * x1, x1 * y1, y1 * y1, x1, y1, 1.f};
        float wn[6];
        wn[0] = w * (x2 * x2);
        wn[1] = w * (x2 * y2);
        wn[2] = w * (y2 * y2);
        wn[3] = w * x2;
        wn[4] = w * y2;
        wn[5] = w;
#pragma unroll
        for (int pI = 0; pI < 6; pI++)
#pragma unroll
            for (int q = 0; q < 6; q++)
                acc[pI * 6 + q] = fmaf(wn[pI], mmv[q], acc[pI * 6 + q]);
    }

    // warp tree reduce (deterministic)
#pragma unroll
    for (int k = 0; k < 36; k++) {
#pragma unroll
        for (int off = 16; off > 0; off >>= 1)
            acc[k] += __shfl_xor_sync(0xffffffffu, acc[k], off);
    }

    __shared__ float sm[TPB / 32][36];
    int wid = threadIdx.x >> 5, lane = threadIdx.x & 31;
    if (lane == 0) {
#pragma unroll
        for (int k = 0; k < 36; k++) sm[wid][k] = acc[k];
    }
    __syncthreads();
    if (threadIdx.x < 36) {
        float s = 0.f;
#pragma unroll
        for (int w8 = 0; w8 < TPB / 32; w8++) s += sm[w8][threadIdx.x];
        g_part[(b * KB + blk) * 36 + threadIdx.x] = s;
    }
}

// ---------------------------------------------------------------------------
// LAPACK ssyevd emulation helpers (fp32, netlib conventions)
// ---------------------------------------------------------------------------
__device__ __forceinline__ float slapy2f(float xx, float yy) {
    float xa = fabsf(xx), ya = fabsf(yy);
    float w = fmaxf(xa, ya);
    float z = fminf(xa, ya);
    if (z == 0.f) return w;
    float q = z / w;
    return w * sqrtf(1.f + q * q);
}

// modern (LAPACK >= 3.10) slartg
__device__ __forceinline__ void slartg_(float f, float g, float& c, float& s, float& r) {
    if (g == 0.f) { c = 1.f; s = 0.f; r = f; }
    else if (f == 0.f) { c = 0.f; s = copysignf(1.f, g); r = fabsf(g); }
    else {
        float dd = sqrtf(f * f + g * g);
        c = fabsf(f) / dd;
        r = copysignf(dd, f);
        s = g / r;
    }
}

__device__ void slaev2_(float a, float b, float c,
                        float& rt1, float& rt2, float& cs1, float& sn1) {
    float sm = a + c, df = a - c, adf = fabsf(df);
    float tb = b + b, ab = fabsf(tb);
    float acmx, acmn;
    if (fabsf(a) > fabsf(c)) { acmx = a; acmn = c; } else { acmx = c; acmn = a; }
    float rt;
    if (adf > ab)      { float q = ab / adf; rt = adf * sqrtf(1.f + q * q); }
    else if (adf < ab) { float q = adf / ab; rt = ab * sqrtf(1.f + q * q); }
    else               { rt = ab * sqrtf(2.f); }
    int sgn1;
    if (sm < 0.f)      { rt1 = 0.5f * (sm - rt); sgn1 = -1; rt2 = (acmx / rt1) * acmn - (b / rt1) * b; }
    else if (sm > 0.f) { rt1 = 0.5f * (sm + rt); sgn1 =  1; rt2 = (acmx / rt1) * acmn - (b / rt1) * b; }
    else               { rt1 = 0.5f * rt; rt2 = -0.5f * rt; sgn1 = 1; }
    int sgn2; float cs;
    if (df >= 0.f) { cs = df + rt; sgn2 = 1; } else { cs = df - rt; sgn2 = -1; }
    float acs = fabsf(cs);
    if (acs > ab) {
        float ct = -tb / cs;
        sn1 = 1.f / sqrtf(1.f + ct * ct);
        cs1 = ct * sn1;
    } else {
        if (ab == 0.f) { cs1 = 1.f; sn1 = 0.f; }
        else {
            float tn = -cs / tb;
            cs1 = 1.f / sqrtf(1.f + tn * tn);
            sn1 = tn * cs1;
        }
    }
    if (sgn1 == sgn2) { float tn = cs1; cs1 = -sn1; sn1 = tn; }
}

// rotation on z columns (col, col+1), lane-parallel: lane r owns row r.
#define ROTZ(col, c, s)                                                    \
    do {                                                                   \
        if (lane < 9) {                                                    \
            float t_  = zs[lane][(col) + 1];                               \
            float u0_ = zs[lane][(col)];                                   \
            zs[lane][(col) + 1] = (c) * t_ - (s) * u0_;                    \
            zs[lane][(col)]     = (s) * t_ + (c) * u0_;                    \
        }                                                                  \
    } while (0)

// ---------------------------------------------------------------------------
// Kernel 2: one warp per batch. Scalar chain runs redundantly on all lanes
// (identical values -> uniform branches -> warp stays converged; same-address
// shared writes carry identical bits). O(n^2) work is lane-parallel.
// Arithmetic orders are expression-identical to the round-2 serial solver.
// ---------------------------------------------------------------------------
__global__ void __launch_bounds__(32) solve_kernel(float* __restrict__ out) {
    int b = blockIdx.x;
    int lane = threadIdx.x;
    const int n = 9;

    __shared__ float S[36];
    __shared__ float A[9][9];
    __shared__ float zs[9][10];
    __shared__ float dsh[9], esh[9], tash[8], wsh[9];

    for (int j = lane; j < 36; j += 32) {
        float s = 0.f;
        for (int k = 0; k < KB; k++) s += g_part[(b * KB + k) * 36 + j];
        S[j] = s;
    }
    __syncwarp();

    // reconstruct 9x9: M[3a+bb][3c+dd] = S[P[a][c]][P[bb][dd]]
    const int Pm[9] = {0, 1, 3, 1, 2, 4, 3, 4, 5};
    for (int idx = lane; idx < 81; idx += 32) {
        int i = idx / 9, j = idx % 9;
        int a = i / 3, bb = i % 3, c = j / 3, dd = j % 3;
        A[i][j] = S[Pm[a * 3 + c] * 6 + Pm[bb * 3 + dd]];
    }
    __syncwarp();

    // ---- ssytrd (uplo='L', unblocked ssytd2) ----
    for (int i = 0; i < n - 1; i++) {
        float alpha = A[i + 1][i];
        float xn2 = 0.f;
        for (int k = i + 2; k < n; k++) xn2 += A[k][i] * A[k][i];
        float taui, beta;
        if (xn2 == 0.f) { taui = 0.f; beta = alpha; }
        else {
            beta = -copysignf(slapy2f(alpha, sqrtf(xn2)), alpha);
            taui = (beta - alpha) / beta;
            float inv = 1.f / (alpha - beta);
            __syncwarp();
            if (lane >= i + 2 && lane < n) A[lane][i] *= inv;
        }
        __syncwarp();
        esh[i]  = beta;     // all lanes write identical value
        tash[i] = taui;
        if (taui != 0.f) {
            // w[r] = taui * sum_cc A[r][cc]*v[cc]   (lane r, serial cc order)
            if (lane >= i + 1 && lane < n) {
                float s = 0.f;
                for (int cc = i + 1; cc < n; cc++) {
                    float vcc = (cc == i + 1) ? 1.f : A[cc][i];
                    s += A[lane][cc] * vcc;
                }
                wsh[lane] = taui * s;
            }
            __syncwarp();
            float dot = 0.f;
            for (int r = i + 1; r < n; r++) {
                float vr = (r == i + 1) ? 1.f : A[r][i];
                dot += wsh[r] * vr;
            }
            float al = -0.5f * taui * dot;
            __syncwarp();
            if (lane >= i + 1 && lane < n) {
                float vl = (lane == i + 1) ? 1.f : A[lane][i];
                wsh[lane] += al * vl;
            }
            __syncwarp();
            if (lane >= i + 1 && lane < n) {
                float vl = (lane == i + 1) ? 1.f : A[lane][i];
                float wl = wsh[lane];
                for (int cc = i + 1; cc < n; cc++) {
                    float vcc = (cc == i + 1) ? 1.f : A[cc][i];
                    A[lane][cc] -= vl * wsh[cc] + wl * vcc;
                }
            }
            __syncwarp();
        }
    }
    if (lane < n) dsh[lane] = A[lane][lane];
    __syncwarp();

    // ---- form Q = H(0) ... H(n-2): lane c owns column c ----
    if (lane < n) {
        for (int r = 0; r < n; r++) zs[r][lane] = (r == lane) ? 1.f : 0.f;
    }
    __syncwarp();
    for (int i = n - 2; i >= 0; i--) {
        float taui = tash[i];
        if (taui == 0.f) continue;
        if (lane < n) {
            float s = 0.f;
            for (int r = i + 1; r < n; r++) {
                float ur = (r == i + 1) ? 1.f : A[r][i];
                s += ur * zs[r][lane];
            }
            s *= taui;
            for (int r = i + 1; r < n; r++) {
                float ur = (r == i + 1) ? 1.f : A[r][i];
                zs[r][lane] -= ur * s;
            }
        }
        __syncwarp();
    }
    __syncwarp();
    // from here on, z is row-private to lane r (rotations / swaps)

    // ---- ssteqr (netlib-faithful) ----
    const float eps = 5.9604645e-08f;   // SLAMCH('E') = 2^-24
    const float eps2 = eps * eps;
    const float safmin = 1.17549435e-38f;
    const int nmaxit = n * 30;
    int jtot = 0;
    int l1 = 0;
    while (l1 < n) {
        if (l1 > 0) esh[l1 - 1] = 0.f;
        int m = n - 1;
        for (int k = l1; k < n - 1; k++) {
            float tst = fabsf(esh[k]);
            if (tst == 0.f) { m = k; break; }
            if (tst <= (sqrtf(fabsf(dsh[k])) * sqrtf(fabsf(dsh[k + 1]))) * eps) {
                esh[k] = 0.f; m = k; break;
            }
        }
        int l = l1, lsv = l, lend = m, lendsv = lend;
        l1 = m + 1;
        if (lend == l) continue;
        if (fabsf(dsh[lend]) < fabsf(dsh[l])) { lend = lsv; l = lendsv; }

        if (lend > l) {
            // --- QL ---
            for (;;) {
                int mm = lend;
                if (l != lend) {
                    for (int k = l; k <= lend - 1; k++) {
                        float tst = esh[k] * esh[k];
                        if (tst <= (eps2 * fabsf(dsh[k])) * fabsf(dsh[k + 1]) + safmin) { mm = k; break; }
                    }
                }
                if (mm < lend) esh[mm] = 0.f;
                float p = dsh[l];
                if (mm == l) {
                    dsh[l] = p; l++;
                    if (l <= lend) continue; else break;
                }
                if (mm == l + 1) {
                    float rt1, rt2, c, s;
                    slaev2_(dsh[l], esh[l], dsh[l + 1], rt1, rt2, c, s);
                    ROTZ(l, c, s);
                    dsh[l] = rt1; dsh[l + 1] = rt2; esh[l] = 0.f;
                    l += 2;
                    if (l <= lend) continue; else break;
                }
                if (jtot == nmaxit) break;
                jtot++;
                float g = (dsh[l + 1] - p) / (2.f * esh[l]);
                float r = slapy2f(g, 1.f);
                g = dsh[mm] - p + esh[l] / (g + copysignf(r, g));
                float s = 1.f, c = 1.f;
                p = 0.f;
                for (int i = mm - 1; i >= l; i--) {
                    float f = s * esh[i];
                    float bb = c * esh[i];
                    slartg_(g, f, c, s, r);
                    if (i != mm - 1) esh[i + 1] = r;
                    g = dsh[i + 1] - p;
                    r = (dsh[i] - g) * s + 2.f * c * bb;
                    p = s * r;
                    dsh[i + 1] = g + p;
                    g = c * r - bb;
                    ROTZ(i, c, -s);          // WORK stores -S, applied 'B'
                }
                dsh[l] -= p;
                esh[l] = g;
            }
        } else {
            // --- QR ---
            for (;;) {
                int mm = lend;
                if (l != lend) {
                    for (int k = l; k >= lend + 1; k--) {
                        float tst = esh[k - 1] * esh[k - 1];
                        if (tst <= (eps2 * fabsf(dsh[k])) * fabsf(dsh[k - 1]) + safmin) { mm = k; break; }
                    }
                }
                if (mm > lend) esh[mm - 1] = 0.f;
                float p = dsh[l];
                if (mm == l) {
                    dsh[l] = p; l--;
                    if (l >= lend) continue; else break;
                }
                if (mm == l - 1) {
                    float rt1, rt2, c, s;
                    slaev2_(dsh[l - 1], esh[l - 1], dsh[l], rt1, rt2, c, s);
                    ROTZ(l - 1, c, s);
                    dsh[l - 1] = rt1; dsh[l] = rt2; esh[l - 1] = 0.f;
                    l -= 2;
                    if (l >= lend) continue; else break;
                }
                if (jtot == nmaxit) break;
                jtot++;
                float g = (dsh[l - 1] - p) / (2.f * esh[l - 1]);
                float r = slapy2f(g, 1.f);
                g = dsh[mm] - p + esh[l - 1] / (g + copysignf(r, g));
                float s = 1.f, c = 1.f;
                p = 0.f;
                for (int i = mm; i <= l - 1; i++) {
                    float f = s * esh[i];
                    float bb = c * esh[i];
                    slartg_(g, f, c, s, r);
                    if (i != mm) esh[i - 1] = r;
                    g = dsh[i] - p;
                    r = (dsh[i + 1] - g) * s + 2.f * c * bb;
                    p = s * r;
                    dsh[i] = g + p;
                    g = c * r - bb;
                    ROTZ(i, c, s);           // WORK stores +S, applied 'F'
                }
                dsh[l] -= p;
                esh[l - 1] = g;
            }
        }
    }

    // ---- selection sort ascending (lane r swaps its own row entries) ----
    for (int ii = 1; ii < n; ii++) {
        int i = ii - 1, k = i;
        float p = dsh[i];
        for (int j = ii; j < n; j++)
            if (dsh[j] < p) { k = j; p = dsh[j]; }
        if (k != i) {
            float di = dsh[i];
            dsh[k] = di; dsh[i] = p;     // all lanes write identical values
            if (lane < n) {
                float tz = zs[lane][i]; zs[lane][i] = zs[lane][k]; zs[lane][k] = tz;
            }
        }
    }
    __syncwarp();

    // ---- output: first column (smallest eigenvalue), normalized ----
    float nrm2 = 0.f;
    for (int r = 0; r < n; r++) nrm2 += zs[r][0] * zs[r][0];
    float inv = 1.f / sqrtf(nrm2);
    if (lane < n) out[b * 9 + lane] = zs[lane][0] * inv;
}

// ---------------------------------------------------------------------------
extern "C" void kernel_launch(void* const* d_in, const int* in_sizes, int n_in,
                              void* d_out, int out_size) {
    const float4* x  = (const float4*)d_in[0];
    const float*  lg = (const float*)d_in[1];
    float* out = (float*)d_out;
    dim3 grid(KB, BATCH);
    reduce_kernel<<<grid, TPB>>>(x, lg);
    solve_kernel<<<BATCH, 32>>>(out);
}